// round 2
// baseline (speedup 1.0000x reference)
#include <cuda_runtime.h>
#include <math.h>

#define N_NODES 5000
#define DEG 16
#define S 17
#define T 10
#define MN 10
#define D 128
#define EPS 0.1f
#define N_OUTER 3
#define N_SINK 5
#define SM_CELLS (S*MN)   // 170

// ---------------- device-global precomputed state / scratch ----------------
__device__ float g_alpha;
__device__ float g_C2[T*MN*MN];     // softmax(templates, axis=1), row-major [t][i][j]
__device__ float g_q[T*MN];         // softmax(q0, axis=1)
__device__ float g_hC2[T*MN];       // sum_j C2[t,i,j]^2 * q[t,j]
__device__ float g_f2sq[T*MN];      // ||F2[t,m]||^2
__device__ float g_M[(size_t)N_NODES * T * S * MN];   // 34 MB scratch: feature cost

// ---------------- kernel 0: tiny precompute -------------------------------
__global__ void precompute_kernel(const float* __restrict__ tmpl,
                                  const float* __restrict__ tf,
                                  const float* __restrict__ q0,
                                  const float* __restrict__ alpha0) {
    int tid = threadIdx.x;
    if (tid == 0) g_alpha = 1.0f / (1.0f + expf(-alpha0[0]));

    // q[t] = softmax over MN of q0[t]
    if (tid < T) {
        float mx = -1e30f;
        for (int m = 0; m < MN; m++) mx = fmaxf(mx, q0[tid*MN + m]);
        float s = 0.f, e[MN];
        for (int m = 0; m < MN; m++) { e[m] = expf(q0[tid*MN + m] - mx); s += e[m]; }
        for (int m = 0; m < MN; m++) g_q[tid*MN + m] = e[m] / s;
    }
    // C2[t,:,j] = softmax over i (axis=1) of templates[t,:,j]
    if (tid < T*MN) {
        int t = tid / MN, j = tid % MN;
        float mx = -1e30f;
        for (int i = 0; i < MN; i++) mx = fmaxf(mx, tmpl[(t*MN + i)*MN + j]);
        float s = 0.f, e[MN];
        for (int i = 0; i < MN; i++) { e[i] = expf(tmpl[(t*MN + i)*MN + j] - mx); s += e[i]; }
        for (int i = 0; i < MN; i++) g_C2[(t*MN + i)*MN + j] = e[i] / s;
    }
    // ||F2[t,m]||^2
    if (tid < T*MN) {
        float s = 0.f;
        const float* row = tf + (size_t)tid * D;
        for (int d = 0; d < D; d++) s += row[d] * row[d];
        g_f2sq[tid] = s;
    }
    __syncthreads();
    // hC2[t,i] = sum_j C2[t,i,j]^2 * q[t,j]
    if (tid < T*MN) {
        int t = tid / MN, i = tid % MN;
        float s = 0.f;
        for (int j = 0; j < MN; j++) {
            float c = g_C2[(t*MN + i)*MN + j];
            s += c * c * g_q[t*MN + j];
        }
        g_hC2[tid] = s;
    }
}

// ---------------- kernel 1: feature cost M ---------------------------------
// M[n,t,s,m] = ||x[local_s]||^2 + ||F2[t,m]||^2 - 2 * <x[local_s], F2[t,m]>
__global__ __launch_bounds__(256) void m_kernel(const float* __restrict__ x,
                                                const int* __restrict__ dst,
                                                const float* __restrict__ tf) {
    // xl is accessed via float4 — must be 16B aligned (R1 failure: it was placed
    // at shared offset 68 after ids[] with only 4B natural alignment).
    __shared__ __align__(16) float xl[S][D];
    __shared__ float xsq[S];
    __shared__ int   ids[S];
    int n = blockIdx.x, tid = threadIdx.x;

    if (tid == 0)          ids[0]   = n;
    else if (tid <= DEG)   ids[tid] = dst[n*DEG + tid - 1];
    __syncthreads();

    for (int idx = tid; idx < S*(D/4); idx += blockDim.x) {
        int r = idx / (D/4), c = idx % (D/4);
        ((float4*)xl[r])[c] = ((const float4*)(x + (size_t)ids[r]*D))[c];
    }
    __syncthreads();
    if (tid < S) {
        float s = 0.f;
        for (int d = 0; d < D; d++) s += xl[tid][d] * xl[tid][d];
        xsq[tid] = s;
    }
    __syncthreads();

    for (int c = tid; c < T*S*MN; c += blockDim.x) {
        int t = c / (S*MN);
        int s = (c / MN) % S;
        int m = c % MN;
        const float4* a = (const float4*)xl[s];
        const float4* b = (const float4*)(tf + (size_t)(t*MN + m)*D);
        float dot = 0.f;
        #pragma unroll 8
        for (int d = 0; d < D/4; d++) {
            float4 av = a[d], bv = b[d];
            dot += av.x*bv.x + av.y*bv.y + av.z*bv.z + av.w*bv.w;
        }
        g_M[((size_t)(n*T + t)*S + s)*MN + m] = xsq[s] + g_f2sq[t*MN + m] - 2.f*dot;
    }
}

// ---------------- kernel 2: FGW iterations ---------------------------------
// 1 CTA per node, warp t handles template t. Tile state [17][10] in smem.
__global__ __launch_bounds__(T*32) void ltfgw_kernel(const int* __restrict__ dst,
                                                     float* __restrict__ out) {
    __shared__ float sM[T][S][MN];
    __shared__ float sG[T][S][MN];
    __shared__ float sK[T][S][MN];
    __shared__ float sH[T][S][MN];
    __shared__ float sC2[T][MN][MN];
    __shared__ float shC2[T][MN];
    __shared__ float sq[T][MN];
    __shared__ float sw_[T][S];
    __shared__ float sv_[T][MN];
    __shared__ unsigned smask[S];
    __shared__ int ids[S];

    int n = blockIdx.x, tid = threadIdx.x;

    if (tid < S) {
        ids[tid] = (tid == 0) ? n : dst[n*DEG + tid - 1];
        smask[tid] = 0u;
    }
    for (int i = tid; i < T*MN*MN; i += blockDim.x) ((float*)sC2)[i] = g_C2[i];
    for (int i = tid; i < T*MN;    i += blockDim.x) { ((float*)shC2)[i] = g_hC2[i]; ((float*)sq)[i] = g_q[i]; }
    for (int i = tid; i < T*SM_CELLS; i += blockDim.x) ((float*)sM)[i] = g_M[(size_t)n*T*SM_CELLS + i];
    __syncthreads();

    // local 1-hop adjacency as bitmasks: adj | adj^T, then zero diagonal
    for (int e = tid; e < S*DEG; e += blockDim.x) {
        int a = e / DEG, k = e % DEG;
        int nb = dst[ids[a]*DEG + k];
        #pragma unroll
        for (int b = 0; b < S; b++) {
            if (ids[b] == nb) { atomicOr(&smask[a], 1u << b); atomicOr(&smask[b], 1u << a); }
        }
    }
    __syncthreads();
    if (tid < S) smask[tid] &= ~(1u << tid);
    __syncthreads();

    float alpha = g_alpha;
    float oma = 1.0f - alpha;
    const float invEps = 1.0f / EPS;

    // G init = p q^T
    for (int i = tid; i < T*SM_CELLS; i += blockDim.x) {
        int t0 = i / SM_CELLS, m0 = i % MN;
        ((float*)sG)[i] = (1.0f / S) * sq[t0][m0];
    }
    __syncthreads();

    int t = tid >> 5, lane = tid & 31;

    for (int it = 0; it < N_OUTER; it++) {
        // P1: H = G @ C2^T   (H[j,l] = sum_k G[j,k] C2[l,k])
        for (int c = lane; c < SM_CELLS; c += 32) {
            int j = c / MN, l = c % MN;
            float acc = 0.f;
            #pragma unroll
            for (int k = 0; k < MN; k++) acc += sG[t][j][k] * sC2[t][l][k];
            sH[t][j][l] = acc;
        }
        __syncwarp();
        // P2: cost -> row-shifted kernel K (exact Sinkhorn invariant:
        // multiplying row i of K by a constant is absorbed by w_i)
        for (int c = lane; c < SM_CELLS; c += 32) {
            int i = c / MN, l = c % MN;
            unsigned mk = smask[i];
            float hc1 = __popc(mk) * (1.0f / S);
            float acc = 0.f;
            while (mk) { int j = __ffs(mk) - 1; mk &= mk - 1; acc += sH[t][j][l]; }
            float tens = hc1 + shC2[t][l] - 2.f * acc;
            float cost = oma * sM[t][i][l] + 2.f * alpha * tens;
            float shift = oma * sM[t][i][0];
            sK[t][i][l] = __expf((shift - cost) * invEps);
        }
        if (lane < MN) sv_[t][lane] = 1.0f;
        __syncwarp();
        // P3: Sinkhorn in scaling domain
        #pragma unroll
        for (int si = 0; si < N_SINK; si++) {
            if (lane < S) {
                float acc = 0.f;
                #pragma unroll
                for (int m2 = 0; m2 < MN; m2++) acc += sK[t][lane][m2] * sv_[t][m2];
                sw_[t][lane] = __fdividef(1.0f / S, acc);
            }
            __syncwarp();
            if (lane < MN) {
                float acc = 0.f;
                #pragma unroll
                for (int s2 = 0; s2 < S; s2++) acc += sK[t][s2][lane] * sw_[t][s2];
                sv_[t][lane] = __fdividef(sq[t][lane], acc);
            }
            __syncwarp();
        }
        // P4: G = K .* (w v^T)
        for (int c = lane; c < SM_CELLS; c += 32) {
            int i = c / MN, l = c % MN;
            sG[t][i][l] = sK[t][i][l] * sw_[t][i] * sv_[t][l];
        }
        __syncwarp();
    }

    // final tens with final G, then dist = sum G .* ((1-a)M + a*tens)
    for (int c = lane; c < SM_CELLS; c += 32) {
        int j = c / MN, l = c % MN;
        float acc = 0.f;
        #pragma unroll
        for (int k = 0; k < MN; k++) acc += sG[t][j][k] * sC2[t][l][k];
        sH[t][j][l] = acc;
    }
    __syncwarp();
    float acc = 0.f;
    for (int c = lane; c < SM_CELLS; c += 32) {
        int i = c / MN, l = c % MN;
        unsigned mk = smask[i];
        float hc1 = __popc(mk) * (1.0f / S);
        float a2 = 0.f;
        while (mk) { int j = __ffs(mk) - 1; mk &= mk - 1; a2 += sH[t][j][l]; }
        float tens = hc1 + shC2[t][l] - 2.f * a2;
        acc += sG[t][i][l] * (oma * sM[t][i][l] + alpha * tens);
    }
    #pragma unroll
    for (int off = 16; off; off >>= 1) acc += __shfl_down_sync(0xffffffffu, acc, off);
    if (lane == 0) out[n*T + t] = acc;
}

// ---------------- launch ----------------------------------------------------
extern "C" void kernel_launch(void* const* d_in, const int* in_sizes, int n_in,
                              void* d_out, int out_size) {
    const float* x      = (const float*)d_in[0];
    const int*   edge   = (const int*)  d_in[1];
    const float* tmpl   = (const float*)d_in[2];
    const float* tf     = (const float*)d_in[3];
    const float* q0     = (const float*)d_in[4];
    const float* alpha0 = (const float*)d_in[5];
    const int*   dst    = edge + N_NODES*DEG;   // edge_index[1]
    float* out = (float*)d_out;

    precompute_kernel<<<1, 128>>>(tmpl, tf, q0, alpha0);
    m_kernel<<<N_NODES, 256>>>(x, dst, tf);
    ltfgw_kernel<<<N_NODES, T*32>>>(dst, out);
}

// round 3
// speedup vs baseline: 2.4054x; 2.4054x over previous
#include <cuda_runtime.h>
#include <math.h>

#define N_NODES 5000
#define DEG 16
#define S 17
#define T 10
#define MN 10
#define D 128
#define EPS 0.1f
#define N_OUTER 3
#define N_SINK 5
#define TM (T*MN)          // 100
#define NODES_PER_BLK 20

#define FULLMASK 0xffffffffu
// full-warp butterfly sum (inactive lanes must contribute 0)
#define BFLY_SUM(x) do { \
    x += __shfl_xor_sync(FULLMASK, x, 16); \
    x += __shfl_xor_sync(FULLMASK, x, 8);  \
    x += __shfl_xor_sync(FULLMASK, x, 4);  \
    x += __shfl_xor_sync(FULLMASK, x, 2);  \
    x += __shfl_xor_sync(FULLMASK, x, 1);  \
} while (0)

// ---------------- device-global precomputed state / scratch ----------------
__device__ float g_alpha;
__device__ float g_C2[T*MN*MN];     // softmax(templates, axis=1) [t][i][j]
__device__ float g_q[T*MN];         // softmax(q0, axis=1)
__device__ float g_hC2[T*MN];       // sum_j C2[t,i,j]^2 * q[t,j]
__device__ float g_f2sq[T*MN];      // ||F2[t,m]||^2
__device__ float g_Pm[(size_t)N_NODES * TM];  // f2sq[tm] - 2*<x_n, F2_tm>  (2 MB)
__device__ float g_xsq[N_NODES];              // ||x_n||^2

// ---------------- kernel 0: tiny precompute -------------------------------
__global__ void precompute_kernel(const float* __restrict__ tmpl,
                                  const float* __restrict__ tf,
                                  const float* __restrict__ q0,
                                  const float* __restrict__ alpha0) {
    int tid = threadIdx.x;
    if (tid == 0) g_alpha = 1.0f / (1.0f + expf(-alpha0[0]));

    if (tid < T) {
        float mx = -1e30f;
        for (int m = 0; m < MN; m++) mx = fmaxf(mx, q0[tid*MN + m]);
        float s = 0.f, e[MN];
        for (int m = 0; m < MN; m++) { e[m] = expf(q0[tid*MN + m] - mx); s += e[m]; }
        for (int m = 0; m < MN; m++) g_q[tid*MN + m] = e[m] / s;
    }
    if (tid < T*MN) {
        int t = tid / MN, j = tid % MN;
        float mx = -1e30f;
        for (int i = 0; i < MN; i++) mx = fmaxf(mx, tmpl[(t*MN + i)*MN + j]);
        float s = 0.f, e[MN];
        for (int i = 0; i < MN; i++) { e[i] = expf(tmpl[(t*MN + i)*MN + j] - mx); s += e[i]; }
        for (int i = 0; i < MN; i++) g_C2[(t*MN + i)*MN + j] = e[i] / s;
    }
    if (tid < T*MN) {
        float s = 0.f;
        const float4* row = (const float4*)(tf + (size_t)tid * D);
        #pragma unroll 8
        for (int d = 0; d < D/4; d++) {
            float4 v = row[d];
            s += v.x*v.x + v.y*v.y + v.z*v.z + v.w*v.w;
        }
        g_f2sq[tid] = s;
    }
    __syncthreads();
    if (tid < T*MN) {
        int t = tid / MN, i = tid % MN;
        float s = 0.f;
        for (int j = 0; j < MN; j++) {
            float c = g_C2[(t*MN + i)*MN + j];
            s += c * c * g_q[t*MN + j];
        }
        g_hC2[tid] = s;
    }
}

// ---------------- kernel 1: Pm = f2sq - 2 * X @ F2^T  + xsq ----------------
// Dot products shared across all neighborhoods: 64M MAC total (17x less than
// computing per-neighborhood feature costs).
__global__ __launch_bounds__(256) void pm_kernel(const float* __restrict__ x,
                                                 const float* __restrict__ tf) {
    __shared__ __align__(16) float sx[NODES_PER_BLK][D];
    int base = blockIdx.x * NODES_PER_BLK;
    int tid = threadIdx.x;

    for (int idx = tid; idx < NODES_PER_BLK*(D/4); idx += blockDim.x) {
        int r = idx / (D/4), c = idx % (D/4);
        ((float4*)sx[r])[c] = ((const float4*)(x + (size_t)(base + r)*D))[c];
    }
    __syncthreads();
    if (tid < NODES_PER_BLK) {
        float s = 0.f;
        #pragma unroll 8
        for (int d = 0; d < D/4; d++) {
            float4 v = ((float4*)sx[tid])[d];
            s += v.x*v.x + v.y*v.y + v.z*v.z + v.w*v.w;
        }
        g_xsq[base + tid] = s;
    }

    for (int idx = tid; idx < NODES_PER_BLK*TM; idx += blockDim.x) {
        int nl = idx / TM, tm = idx % TM;
        const float4* a = (const float4*)sx[nl];
        const float4* b = (const float4*)(tf + (size_t)tm*D);
        float dot = 0.f;
        #pragma unroll 8
        for (int d = 0; d < D/4; d++) {
            float4 av = a[d], bv = b[d];
            dot += av.x*bv.x + av.y*bv.y + av.z*bv.z + av.w*bv.w;
        }
        g_Pm[(size_t)(base + nl)*TM + tm] = g_f2sq[tm] - 2.f*dot;
    }
}

// ---------------- kernel 2: fully registerized FGW ------------------------
// 1 CTA per node, warp t = template t. Lane i in [0,17) owns row i of the
// 17x10 transport tile in registers. Sinkhorn column sums via shfl butterfly.
// Adjacency structure: smask[0] == {1..16} exactly; smask[i>=1] always has
// bit 0 plus rare extra bits -> A@H = butterfly + broadcast + short loop.
__global__ __launch_bounds__(T*32) void ltfgw_kernel(const int* __restrict__ dst,
                                                     float* __restrict__ out) {
    __shared__ __align__(16) float sC2[T][MN][12];  // padded rows (zeros in pad)
    __shared__ float shC2[T][MN];
    __shared__ float sq_[T][MN];
    __shared__ unsigned smask[S];
    __shared__ int ids[S];

    int n = blockIdx.x, tid = threadIdx.x;

    if (tid < S) {
        ids[tid] = (tid == 0) ? n : dst[n*DEG + tid - 1];
        smask[tid] = 0u;
    }
    for (int idx = tid; idx < T*MN*12; idx += blockDim.x) {
        int t0 = idx / (MN*12), rem = idx % (MN*12);
        int l0 = rem / 12, k0 = rem % 12;
        ((float*)sC2)[idx] = (k0 < MN) ? g_C2[(t0*MN + l0)*MN + k0] : 0.f;
    }
    for (int idx = tid; idx < T*MN; idx += blockDim.x) {
        ((float*)shC2)[idx] = g_hC2[idx];
        ((float*)sq_)[idx]  = g_q[idx];
    }
    __syncthreads();

    // local 1-hop adjacency bitmasks (same semantics as reference)
    for (int e = tid; e < S*DEG; e += blockDim.x) {
        int a = e / DEG, k = e % DEG;
        int nb = dst[ids[a]*DEG + k];
        #pragma unroll
        for (int b = 0; b < S; b++) {
            if (ids[b] == nb) { atomicOr(&smask[a], 1u << b); atomicOr(&smask[b], 1u << a); }
        }
    }
    __syncthreads();
    if (tid < S) smask[tid] &= ~(1u << tid);
    __syncthreads();

    const float alpha = g_alpha;
    const float oma = 1.0f - alpha;
    const float invEps = 1.0f / EPS;

    int t = tid >> 5, lane = tid & 31;
    bool active = lane < S;
    int i = active ? lane : 0;

    unsigned mask_i = active ? smask[i] : 0u;
    float hc1 = __popc(mask_i) * (1.0f / S);
    unsigned extra = (lane == 0 || !active) ? 0u : (mask_i & ~1u);

    // gather M row: M[i][l] = xsq[ids[i]] + Pm[ids[i]][t*MN+l]
    float Mrow[MN];
    {
        int id = ids[i];
        float xs = g_xsq[id];
        const float* pm = g_Pm + (size_t)id*TM + t*MN;
        #pragma unroll
        for (int l = 0; l < MN; l++) Mrow[l] = active ? (xs + pm[l]) : 0.f;
    }

    float qreg[MN], hc2reg[MN];
    #pragma unroll
    for (int l = 0; l < MN; l++) { qreg[l] = sq_[t][l]; hc2reg[l] = shC2[t][l]; }

    // G0 = p q^T  represented as K=q, w=1/S, v=1
    float K[MN], v[MN];
    float w = 1.0f / S;
    #pragma unroll
    for (int l = 0; l < MN; l++) { K[l] = active ? qreg[l] : 0.f; v[l] = 1.f; }

    float H[MN];

    for (int it = 0; it <= N_OUTER; it++) {
        // ---- P1: H[l] = sum_k G[i][k] * C2[l][k],  G = K .* (w v^T) ----
        float Gk[12];
        #pragma unroll
        for (int k = 0; k < MN; k++) Gk[k] = K[k] * v[k] * w;
        Gk[10] = 0.f; Gk[11] = 0.f;
        #pragma unroll
        for (int l = 0; l < MN; l++) {
            const float4* c4 = (const float4*)&sC2[t][l][0];
            float4 c0 = c4[0], c1 = c4[1], c2 = c4[2];
            float h = Gk[0]*c0.x + Gk[1]*c0.y + Gk[2]*c0.z + Gk[3]*c0.w
                    + Gk[4]*c1.x + Gk[5]*c1.y + Gk[6]*c1.z + Gk[7]*c1.w
                    + Gk[8]*c2.x + Gk[9]*c2.y;
            H[l] = active ? h : 0.f;
        }
        // ---- P2: A = adjacency @ H ----
        float A[MN];
        #pragma unroll
        for (int l = 0; l < MN; l++) {
            float s = H[l];
            BFLY_SUM(s);                                 // sum over all rows
            float h0 = __shfl_sync(FULLMASK, H[l], 0);
            A[l] = (lane == 0) ? (s - h0) : h0;          // row0: {1..16}; else bit0
        }
        unsigned ex = extra;
        while (__any_sync(FULLMASK, ex)) {
            bool has = (ex != 0);
            int j = has ? (__ffs(ex) - 1) : 0;
            ex &= ex - 1;
            #pragma unroll
            for (int l = 0; l < MN; l++) {
                float hj = __shfl_sync(FULLMASK, H[l], j);
                if (has) A[l] += hj;
            }
        }

        if (it == N_OUTER) {
            // final distance: sum G .* ((1-a)M + a*tens)
            float acc = 0.f;
            #pragma unroll
            for (int l = 0; l < MN; l++) {
                float tens = hc1 + hc2reg[l] - 2.f * A[l];
                float G = K[l] * v[l] * w;
                acc += G * (oma * Mrow[l] + alpha * tens);
            }
            BFLY_SUM(acc);
            if (lane == 0) out[n*T + t] = acc;
            return;
        }

        // ---- K = exp((shift - cost)/eps), row-shift by (1-a)M[i][0] ----
        #pragma unroll
        for (int l = 0; l < MN; l++) {
            float tens = hc1 + hc2reg[l] - 2.f * A[l];
            float arg = (oma * (Mrow[0] - Mrow[l]) - 2.f * alpha * tens) * invEps;
            K[l] = active ? __expf(arg) : 0.f;
        }
        // ---- P3: Sinkhorn in scaling domain, fully in registers ----
        #pragma unroll
        for (int l = 0; l < MN; l++) v[l] = 1.f;
        #pragma unroll
        for (int si = 0; si < N_SINK; si++) {
            float rs = 0.f;
            #pragma unroll
            for (int l = 0; l < MN; l++) rs += K[l] * v[l];
            w = active ? __fdividef(1.0f / S, rs) : 0.f;
            #pragma unroll
            for (int l = 0; l < MN; l++) {
                float c = K[l] * w;
                BFLY_SUM(c);                 // column sum over rows; all lanes get it
                v[l] = __fdividef(qreg[l], c);
            }
        }
    }
}

// ---------------- launch ----------------------------------------------------
extern "C" void kernel_launch(void* const* d_in, const int* in_sizes, int n_in,
                              void* d_out, int out_size) {
    const float* x      = (const float*)d_in[0];
    const int*   edge   = (const int*)  d_in[1];
    const float* tmpl   = (const float*)d_in[2];
    const float* tf     = (const float*)d_in[3];
    const float* q0     = (const float*)d_in[4];
    const float* alpha0 = (const float*)d_in[5];
    const int*   dst    = edge + N_NODES*DEG;   // edge_index[1]
    float* out = (float*)d_out;

    precompute_kernel<<<1, 128>>>(tmpl, tf, q0, alpha0);
    pm_kernel<<<N_NODES/NODES_PER_BLK, 256>>>(x, tf);
    ltfgw_kernel<<<N_NODES, T*32>>>(dst, out);
}

// round 4
// speedup vs baseline: 5.6697x; 2.3571x over previous
#include <cuda_runtime.h>
#include <math.h>

#define N_NODES 5000
#define DEG 16
#define S 17
#define T 10
#define MN 10
#define D 128
#define EPS 0.1f
#define N_OUTER 3
#define N_SINK 5
#define TM (T*MN)          // 100
#define NPB 10             // nodes per block in pm_kernel
#define LOG2E 1.4426950408889634f
#define FULLMASK 0xffffffffu

#define BFLY_SUM(x) do { \
    x += __shfl_xor_sync(FULLMASK, x, 16); \
    x += __shfl_xor_sync(FULLMASK, x, 8);  \
    x += __shfl_xor_sync(FULLMASK, x, 4);  \
    x += __shfl_xor_sync(FULLMASK, x, 2);  \
    x += __shfl_xor_sync(FULLMASK, x, 1);  \
} while (0)

// ---------------- device-global precomputed state / scratch ----------------
__device__ float g_alpha;
__device__ float g_C2[T*MN*MN];     // softmax(templates, axis=1) [t][l][k]
__device__ float g_q[T*MN];         // softmax(q0, axis=1)
__device__ float g_hC2[T*MN];       // sum_k C2[t,l,k]^2 q[t,k]
__device__ float g_Hq[T*MN];        // sum_k q[t,k] C2[t,l,k]  (column-marginal identity)
__device__ float g_f2sq[T*MN];      // ||F2[t,m]||^2
__device__ float g_Pm[(size_t)N_NODES * TM];  // f2sq[tm] - 2<x_n,F2_tm>  (2MB)
__device__ float g_xsq[N_NODES];

// ---------------- kernel 0: tiny precompute -------------------------------
__global__ void precompute_kernel(const float* __restrict__ tmpl,
                                  const float* __restrict__ tf,
                                  const float* __restrict__ q0,
                                  const float* __restrict__ alpha0) {
    int tid = threadIdx.x;
    if (tid == 0) g_alpha = 1.0f / (1.0f + expf(-alpha0[0]));

    if (tid < T) {
        float mx = -1e30f;
        for (int m = 0; m < MN; m++) mx = fmaxf(mx, q0[tid*MN + m]);
        float s = 0.f, e[MN];
        for (int m = 0; m < MN; m++) { e[m] = expf(q0[tid*MN + m] - mx); s += e[m]; }
        for (int m = 0; m < MN; m++) g_q[tid*MN + m] = e[m] / s;
    }
    if (tid < T*MN) {
        int t = tid / MN, j = tid % MN;
        float mx = -1e30f;
        for (int i = 0; i < MN; i++) mx = fmaxf(mx, tmpl[(t*MN + i)*MN + j]);
        float s = 0.f, e[MN];
        for (int i = 0; i < MN; i++) { e[i] = expf(tmpl[(t*MN + i)*MN + j] - mx); s += e[i]; }
        for (int i = 0; i < MN; i++) g_C2[(t*MN + i)*MN + j] = e[i] / s;
    }
    if (tid < T*MN) {
        float s = 0.f;
        const float4* row = (const float4*)(tf + (size_t)tid * D);
        #pragma unroll 8
        for (int d = 0; d < D/4; d++) {
            float4 v = row[d];
            s += v.x*v.x + v.y*v.y + v.z*v.z + v.w*v.w;
        }
        g_f2sq[tid] = s;
    }
    __syncthreads();
    if (tid < T*MN) {
        int t = tid / MN, l = tid % MN;
        float s = 0.f, hq = 0.f;
        for (int k = 0; k < MN; k++) {
            float c = g_C2[(t*MN + l)*MN + k];
            float qq = g_q[t*MN + k];
            s += c * c * qq;
            hq += c * qq;
        }
        g_hC2[tid] = s;
        g_Hq[tid]  = hq;
    }
}

// ---------------- kernel 1: Pm = f2sq - 2 * X @ F2^T ----------------------
// Register-tiled: thread owns (nl, 4 tms). Lanes share tf rows (broadcast
// LDG), sx staged in smem. 16 FMA per 5 wide loads.
__global__ __launch_bounds__(256) void pm_kernel(const float* __restrict__ x,
                                                 const float* __restrict__ tf) {
    __shared__ __align__(16) float4 sx4[NPB][D/4];
    int base = blockIdx.x * NPB;
    int tid = threadIdx.x;

    for (int idx = tid; idx < NPB*(D/4); idx += blockDim.x) {
        int r = idx / (D/4), c = idx % (D/4);
        sx4[r][c] = ((const float4*)(x + (size_t)(base + r)*D))[c];
    }
    __syncthreads();
    if (tid < NPB) {
        float s = 0.f;
        #pragma unroll 8
        for (int d = 0; d < D/4; d++) {
            float4 v = sx4[tid][d];
            s += v.x*v.x + v.y*v.y + v.z*v.z + v.w*v.w;
        }
        g_xsq[base + tid] = s;
    }

    if (tid < NPB * (TM/4)) {
        int nl = tid % NPB, tm4 = tid / NPB;   // lanes: nl fastest -> tf bcast
        int tm0 = tm4 * 4;
        const float4* b0 = (const float4*)(tf + (size_t)(tm0+0)*D);
        const float4* b1 = (const float4*)(tf + (size_t)(tm0+1)*D);
        const float4* b2 = (const float4*)(tf + (size_t)(tm0+2)*D);
        const float4* b3 = (const float4*)(tf + (size_t)(tm0+3)*D);
        float a0=0.f, a1=0.f, a2=0.f, a3=0.f;
        #pragma unroll 8
        for (int d = 0; d < D/4; d++) {
            float4 av = sx4[nl][d];
            float4 r0 = b0[d], r1 = b1[d], r2 = b2[d], r3 = b3[d];
            a0 += av.x*r0.x + av.y*r0.y + av.z*r0.z + av.w*r0.w;
            a1 += av.x*r1.x + av.y*r1.y + av.z*r1.z + av.w*r1.w;
            a2 += av.x*r2.x + av.y*r2.y + av.z*r2.z + av.w*r2.w;
            a3 += av.x*r3.x + av.y*r3.y + av.z*r3.z + av.w*r3.w;
        }
        size_t o = (size_t)(base + nl)*TM + tm0;
        g_Pm[o+0] = g_f2sq[tm0+0] - 2.f*a0;
        g_Pm[o+1] = g_f2sq[tm0+1] - 2.f*a1;
        g_Pm[o+2] = g_f2sq[tm0+2] - 2.f*a2;
        g_Pm[o+3] = g_f2sq[tm0+3] - 2.f*a3;
    }
}

// ---------------- kernel 2: registerized FGW, gather-based Sinkhorn --------
// 1 CTA per node, warp t = template t. Lane i<17 owns row i (K, M); lane l<10
// also owns column l (KT, v). Column-marginal identity kills the A@H
// butterfly; Sinkhorn sums via v/w gathers; K transposed via smem per outer.
__global__ __launch_bounds__(T*32) void ltfgw_kernel(const int* __restrict__ dst,
                                                     float* __restrict__ out) {
    __shared__ __align__(16) float sC2[T][MN][12]; // zero-padded rows
    __shared__ float sHq[T][MN];
    __shared__ float sq_[T][MN];
    __shared__ float shC2[T][MN];
    __shared__ float kbuf[T][S][11];               // stride 11: conflict-free
    __shared__ unsigned smask[S];
    __shared__ int ids[S];

    int n = blockIdx.x, tid = threadIdx.x;

    if (tid < S) {
        ids[tid] = (tid == 0) ? n : dst[n*DEG + tid - 1];
        smask[tid] = 0u;
    }
    for (int idx = tid; idx < T*MN*12; idx += blockDim.x) {
        int t0 = idx / (MN*12), rem = idx % (MN*12);
        int l0 = rem / 12, k0 = rem % 12;
        ((float*)sC2)[idx] = (k0 < MN) ? g_C2[(t0*MN + l0)*MN + k0] : 0.f;
    }
    for (int idx = tid; idx < T*MN; idx += blockDim.x) {
        ((float*)sHq)[idx]  = g_Hq[idx];
        ((float*)sq_)[idx]  = g_q[idx];
        ((float*)shC2)[idx] = g_hC2[idx];
    }
    __syncthreads();

    // local 1-hop adjacency bitmasks (reference semantics)
    for (int e = tid; e < S*DEG; e += blockDim.x) {
        int a = e / DEG, k = e % DEG;
        int nb = dst[ids[a]*DEG + k];
        #pragma unroll
        for (int b = 0; b < S; b++) {
            if (ids[b] == nb) { atomicOr(&smask[a], 1u << b); atomicOr(&smask[b], 1u << a); }
        }
    }
    __syncthreads();
    if (tid < S) smask[tid] &= ~(1u << tid);
    __syncthreads();

    const float alpha = g_alpha;
    const float oma = 1.0f - alpha;
    const float invEps = 1.0f / EPS;
    const float c3 = 4.0f * alpha * invEps * LOG2E;   // A coefficient in exp2 arg
    const float m2a = -2.0f * alpha;                  // final-dist A coefficient

    int t = tid >> 5, lane = tid & 31;
    bool rowact = lane < S;
    int i = rowact ? lane : 0;

    unsigned mask_i = rowact ? smask[i] : 0u;
    float hc1 = __popc(mask_i) * (1.0f / S);
    unsigned extra = (lane == 0 || !rowact) ? 0u : (mask_i & ~1u);

    // per-lane outer-invariant constants
    float Earg[MN], F[MN];
    {
        int id = ids[i];
        float xs = g_xsq[id];
        const float* pm = g_Pm + (size_t)id*TM + t*MN;
        float M0 = xs + pm[0];
        #pragma unroll
        for (int l = 0; l < MN; l++) {
            float Ml = xs + pm[l];
            float hh = hc1 + shC2[t][l];
            Earg[l] = rowact ? (oma*(M0 - Ml) - 2.f*alpha*hh) * invEps * LOG2E : -1e30f;
            F[l]    = oma*Ml + alpha*hh;
        }
    }
    float qcol = sq_[t][lane < MN ? lane : 0];

    // G0 = p q^T  as K=q/S (w pre-folded), v=1
    float K[MN], KT[S];
    float v = 1.0f, w = 0.f;
    #pragma unroll
    for (int l = 0; l < MN; l++) K[l] = rowact ? sq_[t][l] * (1.0f/S) : 0.f;

    for (int it = 0; it <= N_OUTER; it++) {
        // gather v (cols 0..9) -> G row
        float g[MN];
        #pragma unroll
        for (int l = 0; l < MN; l++) g[l] = K[l] * __shfl_sync(FULLMASK, v, l);

        // H[l] = sum_k g[k] C2[t][l][k]
        float A[MN];
        #pragma unroll
        for (int l = 0; l < MN; l++) {
            const float4* c4 = (const float4*)&sC2[t][l][0];
            float4 c0 = c4[0], c1 = c4[1], c2 = c4[2];
            A[l] = g[0]*c0.x + g[1]*c0.y + g[2]*c0.z + g[3]*c0.w
                 + g[4]*c1.x + g[5]*c1.y + g[6]*c1.z + g[7]*c1.w
                 + g[8]*c2.x + g[9]*c2.y;           // = H[i][l]
        }
        // A = adjacency @ H using colsum(G)=q identity:
        //   row 0 (mask exactly {1..16}): A0[l] = Hq[l] - H[0][l]
        //   rows i>=1: A[l] = H[0][l] (+ rare extras)
        #pragma unroll
        for (int l = 0; l < MN; l++) {
            float h0 = __shfl_sync(FULLMASK, A[l], 0);
            float hq = sHq[t][l];
            A[l] = (lane == 0) ? (hq - A[l]) : h0;
        }
        unsigned ex = extra;
        while (__any_sync(FULLMASK, ex)) {
            bool has = (ex != 0);
            int j = has ? (__ffs(ex) - 1) : 0;
            ex &= ex - 1;
            #pragma unroll
            for (int l = 0; l < MN; l++) {
                // re-derive H[j][l]: H values were overwritten; instead shuffle
                // from lane j BEFORE overwrite is impossible -> keep H copy
                // (handled below by hcopy)
                (void)j; (void)has;
            }
            break; // placeholder; real extras handled via hcopy path below
        }
        // NOTE: extras need original H rows; recompute via hcopy:
        if (__any_sync(FULLMASK, extra)) {
            // recompute H into temp and add extras
            float Hl[MN];
            #pragma unroll
            for (int l = 0; l < MN; l++) {
                const float4* c4 = (const float4*)&sC2[t][l][0];
                float4 c0 = c4[0], c1 = c4[1], c2 = c4[2];
                Hl[l] = g[0]*c0.x + g[1]*c0.y + g[2]*c0.z + g[3]*c0.w
                      + g[4]*c1.x + g[5]*c1.y + g[6]*c1.z + g[7]*c1.w
                      + g[8]*c2.x + g[9]*c2.y;
            }
            unsigned ex2 = extra;
            while (__any_sync(FULLMASK, ex2)) {
                bool has = (ex2 != 0);
                int j = has ? (__ffs(ex2) - 1) : 0;
                ex2 &= ex2 - 1;
                #pragma unroll
                for (int l = 0; l < MN; l++) {
                    float hj = __shfl_sync(FULLMASK, Hl[l], j);
                    if (has) A[l] += hj;
                }
            }
        }

        if (it == N_OUTER) {
            float acc = 0.f;
            #pragma unroll
            for (int l = 0; l < MN; l++) acc += g[l] * fmaf(m2a, A[l], F[l]);
            BFLY_SUM(acc);
            if (lane == 0) out[n*T + t] = acc;
            return;
        }

        // K = exp2(Earg + c3*A)   (row-shifted kernel; shift absorbed by w)
        #pragma unroll
        for (int l = 0; l < MN; l++) K[l] = exp2f(fmaf(c3, A[l], Earg[l]));

        // transpose K -> KT via smem (stride-11 pad: conflict-free)
        __syncwarp();
        if (rowact) {
            #pragma unroll
            for (int l = 0; l < MN; l++) kbuf[t][lane][l] = K[l];
        }
        __syncwarp();
        {
            int ll = lane < MN ? lane : 0;
            #pragma unroll
            for (int ii = 0; ii < S; ii++) KT[ii] = kbuf[t][ii][ll];
            if (lane >= MN) {
                #pragma unroll
                for (int ii = 0; ii < S; ii++) KT[ii] = 0.f;
            }
        }

        // Sinkhorn (scaling domain): gathers instead of butterflies
        v = 1.0f;
        #pragma unroll
        for (int si = 0; si < N_SINK; si++) {
            float rs = 0.f;
            #pragma unroll
            for (int l = 0; l < MN; l++) rs += K[l] * __shfl_sync(FULLMASK, v, l);
            w = rowact ? __fdividef(1.0f / S, rs) : 0.f;
            float cs = 0.f;
            #pragma unroll
            for (int ii = 0; ii < S; ii++) cs += KT[ii] * __shfl_sync(FULLMASK, w, ii);
            v = __fdividef(qcol, cs);
        }
        // fold w into K (w=0 on inactive rows keeps K=0)
        #pragma unroll
        for (int l = 0; l < MN; l++) K[l] *= w;
    }
}

// ---------------- launch ----------------------------------------------------
extern "C" void kernel_launch(void* const* d_in, const int* in_sizes, int n_in,
                              void* d_out, int out_size) {
    const float* x      = (const float*)d_in[0];
    const int*   edge   = (const int*)  d_in[1];
    const float* tmpl   = (const float*)d_in[2];
    const float* tf     = (const float*)d_in[3];
    const float* q0     = (const float*)d_in[4];
    const float* alpha0 = (const float*)d_in[5];
    const int*   dst    = edge + N_NODES*DEG;
    float* out = (float*)d_out;

    precompute_kernel<<<1, 128>>>(tmpl, tf, q0, alpha0);
    pm_kernel<<<N_NODES/NPB, 256>>>(x, tf);
    ltfgw_kernel<<<N_NODES, T*32>>>(dst, out);
}